// round 8
// baseline (speedup 1.0000x reference)
#include <cuda_runtime.h>
#include <cuda_bf16.h>

// PoseProjection: fused rigid-transform trilinear resample.
// CROP = (X=96, Y=96, Z=48), B=8, C=32, VOXEL_SIZE=0.0625 (1/v = 16).
// (ix,iy,iz) = T[:3,:3]*(w,h,d) + T[:3,3]*16,  T = inv(current)@historical.
// Output (concat f32): feat[8,32,48,96,96] | sdf | occ | grid[8,48,96,96,3]
//
// features transposed to channel-last [B,DHW,32]: each corner's 32 channels
// are one aligned 128B line. Corner math computed once per voxel (warp 0),
// shared via smem to the 8 gather threads per voxel.

#define Bn   8
#define Cn   32
#define Dd   48
#define Hh   96
#define Ww   96
#define HW   (Hh * Ww)          // 9216
#define DHW  (Dd * HW)          // 442368
#define FEATN ((size_t)Bn * Cn * DHW)
#define SDFN  ((size_t)Bn * DHW)

__device__ float  g_M[Bn][12];
__device__ float  g_featT[(size_t)Bn * DHW * Cn];    // [B][DHW][32]
__device__ float2 g_soT[(size_t)Bn * DHW];           // [B][DHW] {sdf, occ}

// ---------------------------------------------------------------------------
// Setup: T = inv(current) @ historical (Gauss-Jordan w/ pivoting).
// ---------------------------------------------------------------------------
__global__ void setup_kernel(const float* __restrict__ hist,
                             const float* __restrict__ cur) {
    int b = threadIdx.x;
    if (b >= Bn) return;

    float A[4][4], Inv[4][4];
    for (int i = 0; i < 4; i++)
        for (int j = 0; j < 4; j++) {
            A[i][j]   = cur[b * 16 + i * 4 + j];
            Inv[i][j] = (i == j) ? 1.f : 0.f;
        }
    for (int c = 0; c < 4; c++) {
        int p = c; float mx = fabsf(A[c][c]);
        for (int r = c + 1; r < 4; r++) {
            float v = fabsf(A[r][c]);
            if (v > mx) { mx = v; p = r; }
        }
        if (p != c)
            for (int j = 0; j < 4; j++) {
                float t = A[c][j]; A[c][j] = A[p][j]; A[p][j] = t;
                t = Inv[c][j]; Inv[c][j] = Inv[p][j]; Inv[p][j] = t;
            }
        float f = 1.0f / A[c][c];
        for (int j = 0; j < 4; j++) { A[c][j] *= f; Inv[c][j] *= f; }
        for (int r = 0; r < 4; r++) {
            if (r == c) continue;
            float g = A[r][c];
            for (int j = 0; j < 4; j++) {
                A[r][j]   -= g * A[c][j];
                Inv[r][j] -= g * Inv[c][j];
            }
        }
    }
    for (int i = 0; i < 3; i++)
        for (int j = 0; j < 4; j++) {
            float s = 0.f;
            for (int k = 0; k < 4; k++)
                s += Inv[i][k] * hist[b * 16 + k * 4 + j];
            g_M[b][i * 4 + j] = (j == 3) ? s * 16.0f : s;
        }
}

// ---------------------------------------------------------------------------
// Kernel 1a: transpose feat [B,32,DHW] -> featT [B,DHW,32].
// 32x32 tile, float4 on both gmem sides.
// ---------------------------------------------------------------------------
__global__ void __launch_bounds__(256)
transpose_kernel(const float* __restrict__ feat) {
    __shared__ float s[32][33];
    int b  = blockIdx.y;
    int n0 = blockIdx.x * 32;
    int r = threadIdx.x >> 3;       // 0..31
    int q = threadIdx.x & 7;        // 0..7

    const float* fb = feat + (size_t)b * Cn * DHW;
    float4 v = *(const float4*)(fb + (size_t)r * DHW + n0 + q * 4);
    s[r][q * 4 + 0] = v.x;
    s[r][q * 4 + 1] = v.y;
    s[r][q * 4 + 2] = v.z;
    s[r][q * 4 + 3] = v.w;
    __syncthreads();

    float4 u = make_float4(s[q * 4 + 0][r], s[q * 4 + 1][r],
                           s[q * 4 + 2][r], s[q * 4 + 3][r]);
    *(float4*)(g_featT + ((size_t)b * DHW + n0 + r) * Cn + q * 4) = u;
}

// ---------------------------------------------------------------------------
// Kernel 1b: interleave sdf/occ -> float2.
// ---------------------------------------------------------------------------
__global__ void __launch_bounds__(256)
interleave_kernel(const float* __restrict__ sdf,
                  const float* __restrict__ occ) {
    size_t i = (size_t)blockIdx.x * blockDim.x + threadIdx.x;
    if (i < SDFN) g_soT[i] = make_float2(sdf[i], occ[i]);
}

// ---------------------------------------------------------------------------
// Corner computation.
// ---------------------------------------------------------------------------
__device__ __forceinline__ void corners(const float* __restrict__ M,
                                        int w, int h, int d,
                                        int off[8], float wgt[8],
                                        float& ix, float& iy, float& iz) {
    float fw = (float)w, fh = (float)h, fd = (float)d;
    ix = fmaf(M[0], fw, fmaf(M[1], fh, fmaf(M[2],  fd, M[3])));
    iy = fmaf(M[4], fw, fmaf(M[5], fh, fmaf(M[6],  fd, M[7])));
    iz = fmaf(M[8], fw, fmaf(M[9], fh, fmaf(M[10], fd, M[11])));

    float x0f = floorf(ix), y0f = floorf(iy), z0f = floorf(iz);
    float fx = ix - x0f, fy = iy - y0f, fz = iz - z0f;
    int x0 = (int)x0f, y0 = (int)y0f, z0 = (int)z0f;

    bool vx0 = (x0 >= 0) & (x0 < Ww), vx1 = (x0 + 1 >= 0) & (x0 + 1 < Ww);
    bool vy0 = (y0 >= 0) & (y0 < Hh), vy1 = (y0 + 1 >= 0) & (y0 + 1 < Hh);
    bool vz0 = (z0 >= 0) & (z0 < Dd), vz1 = (z0 + 1 >= 0) & (z0 + 1 < Dd);
    int xc0 = min(max(x0, 0), Ww - 1),     xc1 = min(max(x0 + 1, 0), Ww - 1);
    int yc0 = min(max(y0, 0), Hh - 1),     yc1 = min(max(y0 + 1, 0), Hh - 1);
    int zc0 = min(max(z0, 0), Dd - 1),     zc1 = min(max(z0 + 1, 0), Dd - 1);

    float wx0 = 1.f - fx, wx1 = fx;
    float wy0 = 1.f - fy, wy1 = fy;
    float wz0 = 1.f - fz, wz1 = fz;

    int rb00 = zc0 * HW + yc0 * Ww;
    int rb01 = zc0 * HW + yc1 * Ww;
    int rb10 = zc1 * HW + yc0 * Ww;
    int rb11 = zc1 * HW + yc1 * Ww;

    off[0] = rb00 + xc0; off[1] = rb00 + xc1;
    off[2] = rb01 + xc0; off[3] = rb01 + xc1;
    off[4] = rb10 + xc0; off[5] = rb10 + xc1;
    off[6] = rb11 + xc0; off[7] = rb11 + xc1;

    wgt[0] = (vx0 & vy0 & vz0) ? wx0 * wy0 * wz0 : 0.f;
    wgt[1] = (vx1 & vy0 & vz0) ? wx1 * wy0 * wz0 : 0.f;
    wgt[2] = (vx0 & vy1 & vz0) ? wx0 * wy1 * wz0 : 0.f;
    wgt[3] = (vx1 & vy1 & vz0) ? wx1 * wy1 * wz0 : 0.f;
    wgt[4] = (vx0 & vy0 & vz1) ? wx0 * wy0 * wz1 : 0.f;
    wgt[5] = (vx1 & vy0 & vz1) ? wx1 * wy0 * wz1 : 0.f;
    wgt[6] = (vx0 & vy1 & vz1) ? wx0 * wy1 * wz1 : 0.f;
    wgt[7] = (vx1 & vy1 & vz1) ? wx1 * wy1 * wz1 : 0.f;
}

// ---------------------------------------------------------------------------
// Kernel 2: feature gather. 32 voxels/block. Warp 0 computes corners once,
// shares via smem; also writes the grid output. Then 256 threads gather:
// thread = (voxel, ch4), float4 per corner -> 1 wavefront/corner/voxel.
// ---------------------------------------------------------------------------
__global__ void __launch_bounds__(256)
feat_gather_kernel(float* __restrict__ out) {
    __shared__ int   s_off[32][8];
    __shared__ float s_wgt[32][8];
    __shared__ float s[32][33];

    int b  = blockIdx.y;
    int n0 = blockIdx.x * 32;
    int tid = threadIdx.x;

    if (tid < 32) {
        int n = n0 + tid;
        int w = n % Ww;
        int h = (n / Ww) % Hh;
        int d = n / HW;
        int off[8]; float wgt[8]; float ix, iy, iz;
        corners(g_M[b], w, h, d, off, wgt, ix, iy, iz);
        #pragma unroll
        for (int k = 0; k < 8; k++) {
            s_off[tid][k] = off[k];
            s_wgt[tid][k] = wgt[k];
        }
        // grid output [B,D,H,W,3]
        float* g = out + FEATN + 2 * SDFN + ((size_t)b * DHW + n) * 3;
        g[0] = 2.0f * ix * (1.0f / 95.0f) - 1.0f;
        g[1] = 2.0f * iy * (1.0f / 95.0f) - 1.0f;
        g[2] = 2.0f * iz * (1.0f / 47.0f) - 1.0f;
    }
    __syncthreads();

    int vl  = tid >> 3;      // voxel 0..31
    int ch4 = tid & 7;       // channel group 0..7

    const float* fT = g_featT + (size_t)b * DHW * Cn;
    float4 acc = make_float4(0.f, 0.f, 0.f, 0.f);
    #pragma unroll
    for (int k = 0; k < 8; k++) {
        const float4* p = (const float4*)(fT + (size_t)s_off[vl][k] * Cn) + ch4;
        float4 v = __ldg(p);
        float wk = s_wgt[vl][k];
        acc.x = fmaf(wk, v.x, acc.x);
        acc.y = fmaf(wk, v.y, acc.y);
        acc.z = fmaf(wk, v.z, acc.z);
        acc.w = fmaf(wk, v.w, acc.w);
    }
    int cb = ch4 * 4;
    s[vl][cb + 0] = acc.x;
    s[vl][cb + 1] = acc.y;
    s[vl][cb + 2] = acc.z;
    s[vl][cb + 3] = acc.w;
    __syncthreads();

    // coalesced channel-major stores
    float* ob = out + (size_t)b * Cn * DHW + n0;
    #pragma unroll
    for (int i = 0; i < 4; i++) {
        int idx = i * 256 + tid;
        int nl = idx & 31;
        int c  = idx >> 5;
        ob[(size_t)c * DHW + nl] = s[nl][c];
    }
}

// ---------------------------------------------------------------------------
// Kernel 3: sdf/occ gather (float2 pairs). 1 thread / voxel.
// ---------------------------------------------------------------------------
__global__ void __launch_bounds__(256)
so_kernel(float* __restrict__ out) {
    int b = blockIdx.y;
    int n = blockIdx.x * 256 + threadIdx.x;

    int w = n % Ww;
    int h = (n / Ww) % Hh;
    int d = n / HW;

    int off[8]; float wgt[8]; float ix, iy, iz;
    corners(g_M[b], w, h, d, off, wgt, ix, iy, iz);

    const float2* so = g_soT + (size_t)b * DHW;
    float as = 0.f, ao = 0.f;
    #pragma unroll
    for (int k = 0; k < 8; k++) {
        float2 v = __ldg(so + off[k]);
        as = fmaf(wgt[k], v.x, as);
        ao = fmaf(wgt[k], v.y, ao);
    }
    out[FEATN + (size_t)b * DHW + n]        = as;
    out[FEATN + SDFN + (size_t)b * DHW + n] = ao;
}

extern "C" void kernel_launch(void* const* d_in, const int* in_sizes, int n_in,
                              void* d_out, int out_size) {
    const float* feat = (const float*)d_in[0];
    const float* sdf  = (const float*)d_in[1];
    const float* occ  = (const float*)d_in[2];
    const float* hist = (const float*)d_in[3];
    const float* cur  = (const float*)d_in[4];
    float* out = (float*)d_out;

    setup_kernel<<<1, Bn>>>(hist, cur);

    dim3 gT(DHW / 32, Bn);                 // 13824 x 8
    transpose_kernel<<<gT, 256>>>(feat);

    int ib = (int)((SDFN + 255) / 256);
    interleave_kernel<<<ib, 256>>>(sdf, occ);

    feat_gather_kernel<<<gT, 256>>>(out);

    dim3 gS(DHW / 256, Bn);                // 1728 x 8
    so_kernel<<<gS, 256>>>(out);
}

// round 13
// speedup vs baseline: 1.0891x; 1.0891x over previous
#include <cuda_runtime.h>
#include <cuda_bf16.h>

// PoseProjection: fused rigid-transform trilinear resample.
// CROP = (X=96, Y=96, Z=48), B=8, C=32, VOXEL_SIZE=0.0625 (1/v = 16).
// (ix,iy,iz) = T[:3,:3]*(w,h,d) + T[:3,3]*16,  T = inv(current)@historical.
// Output (concat f32): feat[8,32,48,96,96] | sdf | occ | grid[8,48,96,96,3]
//
// features transposed to channel-last [B,DHW,32]: each corner's 32 channels
// are one aligned 128B line -> exactly 1 L1 wavefront per (voxel, corner).
// Corner math once per voxel; sdf/occ/grid handled in the same phase with
// corner data still in registers. (off,wgt) packed to 8B smem words.

#define Bn   8
#define Cn   32
#define Dd   48
#define Hh   96
#define Ww   96
#define HW   (Hh * Ww)          // 9216
#define DHW  (Dd * HW)          // 442368
#define FEATN ((size_t)Bn * Cn * DHW)
#define SDFN  ((size_t)Bn * DHW)

#define VPB  64                 // voxels per block (feat_gather)

__device__ float  g_M[Bn][12];
__device__ float  g_featT[(size_t)Bn * DHW * Cn];    // [B][DHW][32]
__device__ float2 g_soT[(size_t)Bn * DHW];           // [B][DHW] {sdf, occ}

// ---------------------------------------------------------------------------
// Setup: T = inv(current) @ historical (Gauss-Jordan w/ pivoting).
// ---------------------------------------------------------------------------
__global__ void setup_kernel(const float* __restrict__ hist,
                             const float* __restrict__ cur) {
    int b = threadIdx.x;
    if (b >= Bn) return;

    float A[4][4], Inv[4][4];
    for (int i = 0; i < 4; i++)
        for (int j = 0; j < 4; j++) {
            A[i][j]   = cur[b * 16 + i * 4 + j];
            Inv[i][j] = (i == j) ? 1.f : 0.f;
        }
    for (int c = 0; c < 4; c++) {
        int p = c; float mx = fabsf(A[c][c]);
        for (int r = c + 1; r < 4; r++) {
            float v = fabsf(A[r][c]);
            if (v > mx) { mx = v; p = r; }
        }
        if (p != c)
            for (int j = 0; j < 4; j++) {
                float t = A[c][j]; A[c][j] = A[p][j]; A[p][j] = t;
                t = Inv[c][j]; Inv[c][j] = Inv[p][j]; Inv[p][j] = t;
            }
        float f = 1.0f / A[c][c];
        for (int j = 0; j < 4; j++) { A[c][j] *= f; Inv[c][j] *= f; }
        for (int r = 0; r < 4; r++) {
            if (r == c) continue;
            float g = A[r][c];
            for (int j = 0; j < 4; j++) {
                A[r][j]   -= g * A[c][j];
                Inv[r][j] -= g * Inv[c][j];
            }
        }
    }
    for (int i = 0; i < 3; i++)
        for (int j = 0; j < 4; j++) {
            float s = 0.f;
            for (int k = 0; k < 4; k++)
                s += Inv[i][k] * hist[b * 16 + k * 4 + j];
            g_M[b][i * 4 + j] = (j == 3) ? s * 16.0f : s;
        }
}

// ---------------------------------------------------------------------------
// Kernel 1a: transpose feat [B,32,DHW] -> featT [B,DHW,32].
// 32x32 tile, float4 on both gmem sides.
// ---------------------------------------------------------------------------
__global__ void __launch_bounds__(256)
transpose_kernel(const float* __restrict__ feat) {
    __shared__ float s[32][33];
    int b  = blockIdx.y;
    int n0 = blockIdx.x * 32;
    int r = threadIdx.x >> 3;       // 0..31
    int q = threadIdx.x & 7;        // 0..7

    const float* fb = feat + (size_t)b * Cn * DHW;
    float4 v = *(const float4*)(fb + (size_t)r * DHW + n0 + q * 4);
    s[r][q * 4 + 0] = v.x;
    s[r][q * 4 + 1] = v.y;
    s[r][q * 4 + 2] = v.z;
    s[r][q * 4 + 3] = v.w;
    __syncthreads();

    float4 u = make_float4(s[q * 4 + 0][r], s[q * 4 + 1][r],
                           s[q * 4 + 2][r], s[q * 4 + 3][r]);
    *(float4*)(g_featT + ((size_t)b * DHW + n0 + r) * Cn + q * 4) = u;
}

// ---------------------------------------------------------------------------
// Kernel 1b: interleave sdf/occ -> float2.
// ---------------------------------------------------------------------------
__global__ void __launch_bounds__(256)
interleave_kernel(const float* __restrict__ sdf,
                  const float* __restrict__ occ) {
    size_t i = (size_t)blockIdx.x * blockDim.x + threadIdx.x;
    if (i < SDFN) g_soT[i] = make_float2(sdf[i], occ[i]);
}

// ---------------------------------------------------------------------------
// Corner computation.
// ---------------------------------------------------------------------------
__device__ __forceinline__ void corners(const float* __restrict__ M,
                                        int w, int h, int d,
                                        int off[8], float wgt[8],
                                        float& ix, float& iy, float& iz) {
    float fw = (float)w, fh = (float)h, fd = (float)d;
    ix = fmaf(M[0], fw, fmaf(M[1], fh, fmaf(M[2],  fd, M[3])));
    iy = fmaf(M[4], fw, fmaf(M[5], fh, fmaf(M[6],  fd, M[7])));
    iz = fmaf(M[8], fw, fmaf(M[9], fh, fmaf(M[10], fd, M[11])));

    float x0f = floorf(ix), y0f = floorf(iy), z0f = floorf(iz);
    float fx = ix - x0f, fy = iy - y0f, fz = iz - z0f;
    int x0 = (int)x0f, y0 = (int)y0f, z0 = (int)z0f;

    bool vx0 = (x0 >= 0) & (x0 < Ww), vx1 = (x0 + 1 >= 0) & (x0 + 1 < Ww);
    bool vy0 = (y0 >= 0) & (y0 < Hh), vy1 = (y0 + 1 >= 0) & (y0 + 1 < Hh);
    bool vz0 = (z0 >= 0) & (z0 < Dd), vz1 = (z0 + 1 >= 0) & (z0 + 1 < Dd);
    int xc0 = min(max(x0, 0), Ww - 1),     xc1 = min(max(x0 + 1, 0), Ww - 1);
    int yc0 = min(max(y0, 0), Hh - 1),     yc1 = min(max(y0 + 1, 0), Hh - 1);
    int zc0 = min(max(z0, 0), Dd - 1),     zc1 = min(max(z0 + 1, 0), Dd - 1);

    float wx0 = 1.f - fx, wx1 = fx;
    float wy0 = 1.f - fy, wy1 = fy;
    float wz0 = 1.f - fz, wz1 = fz;

    int rb00 = zc0 * HW + yc0 * Ww;
    int rb01 = zc0 * HW + yc1 * Ww;
    int rb10 = zc1 * HW + yc0 * Ww;
    int rb11 = zc1 * HW + yc1 * Ww;

    off[0] = rb00 + xc0; off[1] = rb00 + xc1;
    off[2] = rb01 + xc0; off[3] = rb01 + xc1;
    off[4] = rb10 + xc0; off[5] = rb10 + xc1;
    off[6] = rb11 + xc0; off[7] = rb11 + xc1;

    wgt[0] = (vx0 & vy0 & vz0) ? wx0 * wy0 * wz0 : 0.f;
    wgt[1] = (vx1 & vy0 & vz0) ? wx1 * wy0 * wz0 : 0.f;
    wgt[2] = (vx0 & vy1 & vz0) ? wx0 * wy1 * wz0 : 0.f;
    wgt[3] = (vx1 & vy1 & vz0) ? wx1 * wy1 * wz0 : 0.f;
    wgt[4] = (vx0 & vy0 & vz1) ? wx0 * wy0 * wz1 : 0.f;
    wgt[5] = (vx1 & vy0 & vz1) ? wx1 * wy0 * wz1 : 0.f;
    wgt[6] = (vx0 & vy1 & vz1) ? wx0 * wy1 * wz1 : 0.f;
    wgt[7] = (vx1 & vy1 & vz1) ? wx1 * wy1 * wz1 : 0.f;
}

// ---------------------------------------------------------------------------
// Kernel 2: fused gather. Block = 256 threads, 64 voxels.
// Phase 1 (threads 0..63): corners once per voxel -> packed smem; with
//   corner data still in registers also gather sdf/occ and write grid.
// Phase 2 (all 256): 2 rounds of (voxel, ch4) float4 feature gathers
//   -> 1 L1 wavefront per (voxel, corner). Staged through smem so
//   channel-major output stores stay coalesced.
// ---------------------------------------------------------------------------
__global__ void __launch_bounds__(256)
feat_gather_kernel(float* __restrict__ out) {
    __shared__ int2  s_ow[VPB][8];     // {off, wgt-bits}
    __shared__ float s[VPB][33];

    int b   = blockIdx.y;
    int n0  = blockIdx.x * VPB;
    int tid = threadIdx.x;

    if (tid < VPB) {
        int n = n0 + tid;
        int w = n % Ww;
        int h = (n / Ww) % Hh;
        int d = n / HW;
        int off[8]; float wgt[8]; float ix, iy, iz;
        corners(g_M[b], w, h, d, off, wgt, ix, iy, iz);
        #pragma unroll
        for (int k = 0; k < 8; k++)
            s_ow[tid][k] = make_int2(off[k], __float_as_int(wgt[k]));

        // sdf/occ gather (registers, no smem round-trip)
        const float2* so = g_soT + (size_t)b * DHW;
        float as = 0.f, ao = 0.f;
        #pragma unroll
        for (int k = 0; k < 8; k++) {
            float2 v = __ldg(so + off[k]);
            as = fmaf(wgt[k], v.x, as);
            ao = fmaf(wgt[k], v.y, ao);
        }
        out[FEATN + (size_t)b * DHW + n]        = as;
        out[FEATN + SDFN + (size_t)b * DHW + n] = ao;

        // grid output [B,D,H,W,3]
        float* g = out + FEATN + 2 * SDFN + ((size_t)b * DHW + n) * 3;
        g[0] = 2.0f * ix * (1.0f / 95.0f) - 1.0f;
        g[1] = 2.0f * iy * (1.0f / 95.0f) - 1.0f;
        g[2] = 2.0f * iz * (1.0f / 47.0f) - 1.0f;
    }
    __syncthreads();

    const float* fT = g_featT + (size_t)b * DHW * Cn;
    #pragma unroll
    for (int r = 0; r < VPB * 8 / 256; r++) {       // 2 rounds
        int task = r * 256 + tid;
        int vl  = task >> 3;        // voxel 0..63
        int ch4 = task & 7;         // channel group 0..7

        float4 acc = make_float4(0.f, 0.f, 0.f, 0.f);
        #pragma unroll
        for (int k = 0; k < 8; k++) {
            int2 ow = s_ow[vl][k];
            const float4* p = (const float4*)(fT + (size_t)ow.x * Cn) + ch4;
            float4 v = __ldg(p);
            float wk = __int_as_float(ow.y);
            acc.x = fmaf(wk, v.x, acc.x);
            acc.y = fmaf(wk, v.y, acc.y);
            acc.z = fmaf(wk, v.z, acc.z);
            acc.w = fmaf(wk, v.w, acc.w);
        }
        int cb = ch4 * 4;
        s[vl][cb + 0] = acc.x;
        s[vl][cb + 1] = acc.y;
        s[vl][cb + 2] = acc.z;
        s[vl][cb + 3] = acc.w;
    }
    __syncthreads();

    // coalesced channel-major stores: 64 voxels x 32 ch = 2048 floats
    float* ob = out + (size_t)b * Cn * DHW + n0;
    #pragma unroll
    for (int i = 0; i < VPB * Cn / 256; i++) {      // 8 rounds
        int idx = i * 256 + tid;
        int nl = idx & (VPB - 1);
        int c  = idx >> 6;
        ob[(size_t)c * DHW + nl] = s[nl][c];
    }
}

extern "C" void kernel_launch(void* const* d_in, const int* in_sizes, int n_in,
                              void* d_out, int out_size) {
    const float* feat = (const float*)d_in[0];
    const float* sdf  = (const float*)d_in[1];
    const float* occ  = (const float*)d_in[2];
    const float* hist = (const float*)d_in[3];
    const float* cur  = (const float*)d_in[4];
    float* out = (float*)d_out;

    setup_kernel<<<1, Bn>>>(hist, cur);

    dim3 gT(DHW / 32, Bn);                 // 13824 x 8
    transpose_kernel<<<gT, 256>>>(feat);

    int ib = (int)((SDFN + 255) / 256);
    interleave_kernel<<<ib, 256>>>(sdf, occ);

    dim3 gG(DHW / VPB, Bn);                // 6912 x 8
    feat_gather_kernel<<<gG, 256>>>(out);
}